// round 6
// baseline (speedup 1.0000x reference)
#include <cuda_runtime.h>
#include <cuda_bf16.h>

// Rule-indexed sparse graph convolution, round 6.
//   out[n,k,f] = sum_{e: src(e)=n} W[k, lab[src], lab[dst], prop(e)] * x[dst(e), f]
//              + b[k, lab[n], f]
//
// Pipeline (2 launches):
//  1. k_prep_scatter : bucket edges by src (packed (lw*16+p)<<15 | d) +
//                      transpose Param_W -> float4 PwT. Cursors self-reset in
//                      k_gather (zero-init statics establish call-1 invariant).
//  2. k_gather : warp-per-node, lane = 4 features. Packed f32x2 datapath:
//                x rows loaded as longlong2 (2x f32x2), accumulation via
//                fma.rn.f32x2 (Blackwell FFMA2) -> 8 FMA-issues/edge instead
//                of 16. Slot words software-pipelined (prefetch next int4).

#define KC 4
#define LC 50
#define PC 16
#define FC 128
#define NN 20000
#define EE 640000
#define LLP (LC * LC * PC)    // 40000, k-stride in Param_W
#define NRULE (LC * LC * PC)  // 40000 rules: (lv*L+lw)*P+p
#define CAP 128               // slots/node; Poisson(32) -> overflow prob ~1e-35

// ---------- static scratch (allocation-free, zero-initialized) ----------
__device__ int    g_cursor[NN];                    // self-resetting (see k_gather)
__device__ __align__(16) int g_slot[NN * CAP];     // packed (lw*PC+p)<<15 | d
__device__ float4 g_PwT[NRULE];                    // {w_k0,w_k1,w_k2,w_k3} per rule

// ---------- packed f32x2 helpers ----------
__device__ __forceinline__ long long pack2(float v) {
    long long r;
    asm("mov.b64 %0, {%1, %1};" : "=l"(r) : "f"(v));
    return r;
}
__device__ __forceinline__ void fma2(long long& a, long long w, long long x) {
    asm("fma.rn.f32x2 %0, %1, %2, %0;" : "+l"(a) : "l"(w), "l"(x));
}
__device__ __forceinline__ long long add2(long long a, long long b) {
    long long r;
    asm("add.rn.f32x2 %0, %1, %2;" : "=l"(r) : "l"(a), "l"(b));
    return r;
}

// ---------- phase 1: scatter + weight transpose (one kernel) ----------
__global__ void __launch_bounds__(256)
k_prep_scatter(const int*   __restrict__ edge_src,
               const int*   __restrict__ edge_dst,
               const int*   __restrict__ edge_prop,
               const int*   __restrict__ labels,
               const float* __restrict__ Pw,
               int E) {
    int t = blockIdx.x * blockDim.x + threadIdx.x;

    // Param_W transpose into float4-per-rule
    if (t < NRULE / 4) {
        const float4* Pw4 = (const float4*)Pw;
        float4 w0 = __ldg(&Pw4[t]);                 // k=0
        float4 w1 = __ldg(&Pw4[t + LLP / 4]);       // k=1
        float4 w2 = __ldg(&Pw4[t + 2 * LLP / 4]);   // k=2
        float4 w3 = __ldg(&Pw4[t + 3 * LLP / 4]);   // k=3
        int b = t * 4;
        g_PwT[b + 0] = make_float4(w0.x, w1.x, w2.x, w3.x);
        g_PwT[b + 1] = make_float4(w0.y, w1.y, w2.y, w3.y);
        g_PwT[b + 2] = make_float4(w0.z, w1.z, w2.z, w3.z);
        g_PwT[b + 3] = make_float4(w0.w, w1.w, w2.w, w3.w);
    }

    // edge bucketing (cursors start at zero via the self-reset invariant)
    if (t < E) {
        int s  = edge_src[t];
        int d  = edge_dst[t];
        int p  = edge_prop[t];
        int lw = __ldg(&labels[d]);
        int pk = ((lw * PC + p) << 15) | d;         // d < 32768, lw*16+p < 800
        int pos = atomicAdd(&g_cursor[s], 1);
        if (pos < CAP) g_slot[s * CAP + pos] = pk;
    }
}

// ---------- phase 2: gather, warp per node, packed f32x2, pipelined ----------
__global__ void __launch_bounds__(128)
k_gather(const float* __restrict__ x,
         const int*   __restrict__ labels,
         const float* __restrict__ Pb,
         float*       __restrict__ out) {
    int warp = (blockIdx.x * blockDim.x + threadIdx.x) >> 5;   // node id
    int lane = threadIdx.x & 31;
    if (warp >= NN) return;
    int n = warp;

    int lv  = labels[n];                   // uniform per warp
    int cnt = g_cursor[n];
    if (cnt > CAP) cnt = CAP;
    if (lane == 0) g_cursor[n] = 0;        // self-reset for next launch/replay

    const int4*      slots4 = (const int4*)(g_slot + n * CAP);   // 16B aligned
    const longlong2* x2     = (const longlong2*)x;  // row = 32 longlong2 (512B)

    // accumulators: [k][lo/hi pair], each = packed 2 floats
    long long aL0 = 0, aH0 = 0, aL1 = 0, aH1 = 0;
    long long aL2 = 0, aH2 = 0, aL3 = 0, aH3 = 0;

    const float4* PwTlv = g_PwT + lv * (LC * PC);   // + (lw*PC+p)

#define ACC_EDGE(W, XV)                                   \
    {                                                     \
        long long p0 = pack2((W).x);                      \
        long long p1 = pack2((W).y);                      \
        long long p2 = pack2((W).z);                      \
        long long p3 = pack2((W).w);                      \
        fma2(aL0, p0, (XV).x); fma2(aH0, p0, (XV).y);     \
        fma2(aL1, p1, (XV).x); fma2(aH1, p1, (XV).y);     \
        fma2(aL2, p2, (XV).x); fma2(aH2, p2, (XV).y);     \
        fma2(aL3, p3, (XV).x); fma2(aH3, p3, (XV).y);     \
    }

    int nIter = cnt >> 2;
    int4 pk = (nIter > 0) ? slots4[0] : make_int4(0, 0, 0, 0);
    for (int it = 0; it < nIter; ++it) {
        int4 cur = pk;
        if (it + 1 < nIter) pk = slots4[it + 1];    // prefetch next slot word

        int d0 = cur.x & 0x7FFF, r0 = cur.x >> 15;
        int d1 = cur.y & 0x7FFF, r1 = cur.y >> 15;
        int d2 = cur.z & 0x7FFF, r2 = cur.z >> 15;
        int d3 = cur.w & 0x7FFF, r3 = cur.w >> 15;

        float4 w0 = __ldg(&PwTlv[r0]);              // warp-broadcast sectors
        float4 w1 = __ldg(&PwTlv[r1]);
        float4 w2 = __ldg(&PwTlv[r2]);
        float4 w3 = __ldg(&PwTlv[r3]);
        longlong2 v0 = x2[d0 * (FC / 4) + lane];    // LDG.128, coalesced
        longlong2 v1 = x2[d1 * (FC / 4) + lane];
        longlong2 v2 = x2[d2 * (FC / 4) + lane];
        longlong2 v3 = x2[d3 * (FC / 4) + lane];

        ACC_EDGE(w0, v0)
        ACC_EDGE(w1, v1)
        ACC_EDGE(w2, v2)
        ACC_EDGE(w3, v3)
    }
    for (int i = nIter << 2; i < cnt; ++i) {
        int pw = g_slot[n * CAP + i];
        int d0 = pw & 0x7FFF, r0 = pw >> 15;
        float4 w0 = __ldg(&PwTlv[r0]);
        longlong2 v0 = x2[d0 * (FC / 4) + lane];
        ACC_EDGE(w0, v0)
    }
#undef ACC_EDGE

    // Epilogue: bias add, everything stays packed; STG.128 stores.
    const longlong2* pb = (const longlong2*)Pb;     // row (k*LC+lv) = 32 longlong2
    longlong2*       o  = (longlong2*)(out + (size_t)n * (KC * FC));

    longlong2 b0 = pb[(0 * LC + lv) * (FC / 4) + lane];
    longlong2 b1 = pb[(1 * LC + lv) * (FC / 4) + lane];
    longlong2 b2 = pb[(2 * LC + lv) * (FC / 4) + lane];
    longlong2 b3 = pb[(3 * LC + lv) * (FC / 4) + lane];

    longlong2 r0; r0.x = add2(aL0, b0.x); r0.y = add2(aH0, b0.y);
    longlong2 r1; r1.x = add2(aL1, b1.x); r1.y = add2(aH1, b1.y);
    longlong2 r2; r2.x = add2(aL2, b2.x); r2.y = add2(aH2, b2.y);
    longlong2 r3; r3.x = add2(aL3, b3.x); r3.y = add2(aH3, b3.y);

    o[0 * (FC / 4) + lane] = r0;
    o[1 * (FC / 4) + lane] = r1;
    o[2 * (FC / 4) + lane] = r2;
    o[3 * (FC / 4) + lane] = r3;
}

extern "C" void kernel_launch(void* const* d_in, const int* in_sizes, int n_in,
                              void* d_out, int out_size) {
    const float* x         = (const float*)d_in[0];
    const int*   labels    = (const int*)  d_in[1];
    const int*   edge_src  = (const int*)  d_in[2];
    const int*   edge_dst  = (const int*)  d_in[3];
    const int*   edge_prop = (const int*)  d_in[4];
    const float* Pw        = (const float*)d_in[5];
    const float* Pb        = (const float*)d_in[6];
    float*       out       = (float*)d_out;

    const int E = in_sizes[2];   // 640000
    (void)n_in; (void)out_size;

    k_prep_scatter<<<(E + 255) / 256, 256>>>(edge_src, edge_dst, edge_prop,
                                             labels, Pw, E);
    k_gather<<<(NN * 32 + 127) / 128, 128>>>(x, labels, Pb, out);
}

// round 7
// speedup vs baseline: 1.4144x; 1.4144x over previous
#include <cuda_runtime.h>
#include <cuda_bf16.h>

// Rule-indexed sparse graph convolution, round 7.
//   out[n,k,f] = sum_{e: src(e)=n} W[k, lab[src], lab[dst], prop(e)] * x[dst(e), f]
//              + b[k, lab[n], f]
//
// Pipeline (2 launches):
//  1. k_prep_scatter : bucket edges by src (packed (lw*16+p)<<15 | d) +
//                      transpose Param_W -> float4 PwT. Cursors self-reset in
//                      k_gather (zero-init statics establish call-1 invariant).
//  2. k_gather : TWO warps per node (feature split). Warp half h owns features
//                [64h, 64h+64); lane = 2 features (float2). Disjoint outputs ->
//                no combine. Halves per-warp serial work, doubles resident
//                warps, cuts regs. fp32 scalar FFMA datapath (R4-proven).

#define KC 4
#define LC 50
#define PC 16
#define FC 128
#define NN 20000
#define EE 640000
#define LLP (LC * LC * PC)    // 40000, k-stride in Param_W
#define NRULE (LC * LC * PC)  // 40000 rules: (lv*L+lw)*P+p
#define CAP 128               // slots/node; Poisson(32) -> overflow prob ~1e-35

// ---------- static scratch (allocation-free, zero-initialized) ----------
__device__ int    g_cursor[NN];                    // self-resetting (see k_gather)
__device__ __align__(16) int g_slot[NN * CAP];     // packed (lw*PC+p)<<15 | d
__device__ float4 g_PwT[NRULE];                    // {w_k0,w_k1,w_k2,w_k3} per rule

// ---------- phase 1: scatter + weight transpose (one kernel) ----------
__global__ void __launch_bounds__(256)
k_prep_scatter(const int*   __restrict__ edge_src,
               const int*   __restrict__ edge_dst,
               const int*   __restrict__ edge_prop,
               const int*   __restrict__ labels,
               const float* __restrict__ Pw,
               int E) {
    int t = blockIdx.x * blockDim.x + threadIdx.x;

    // Param_W transpose into float4-per-rule
    if (t < NRULE / 4) {
        const float4* Pw4 = (const float4*)Pw;
        float4 w0 = __ldg(&Pw4[t]);                 // k=0
        float4 w1 = __ldg(&Pw4[t + LLP / 4]);       // k=1
        float4 w2 = __ldg(&Pw4[t + 2 * LLP / 4]);   // k=2
        float4 w3 = __ldg(&Pw4[t + 3 * LLP / 4]);   // k=3
        int b = t * 4;
        g_PwT[b + 0] = make_float4(w0.x, w1.x, w2.x, w3.x);
        g_PwT[b + 1] = make_float4(w0.y, w1.y, w2.y, w3.y);
        g_PwT[b + 2] = make_float4(w0.z, w1.z, w2.z, w3.z);
        g_PwT[b + 3] = make_float4(w0.w, w1.w, w2.w, w3.w);
    }

    // edge bucketing (cursors start at zero via the self-reset invariant)
    if (t < E) {
        int s  = edge_src[t];
        int d  = edge_dst[t];
        int p  = edge_prop[t];
        int lw = __ldg(&labels[d]);
        int pk = ((lw * PC + p) << 15) | d;         // d < 32768, lw*16+p < 800
        int pos = atomicAdd(&g_cursor[s], 1);
        if (pos < CAP) g_slot[s * CAP + pos] = pk;
    }
}

// ---------- phase 2: gather, 2 warps per node (feature split) ----------
__global__ void __launch_bounds__(256)
k_gather(const float* __restrict__ x,
         const int*   __restrict__ labels,
         const float* __restrict__ Pb,
         float*       __restrict__ out) {
    int gw   = (blockIdx.x * blockDim.x + threadIdx.x) >> 5;  // global warp id
    int lane = threadIdx.x & 31;
    int n    = gw >> 1;          // node id
    int half = gw & 1;           // feature half: 0 -> f[0:64), 1 -> f[64:128)
    // grid is sized exactly: NN*2 warps, no bounds check needed for n < NN
    // (kept for safety against grid rounding)
    bool active = (n < NN);

    int lv  = active ? labels[n] : 0;       // uniform per warp
    int cnt = active ? g_cursor[n] : 0;
    if (cnt > CAP) cnt = CAP;

    // Both sibling warps (same block by construction: 8 warps = 4 nodes/block)
    // must read the cursor before the half-0 warp resets it.
    __syncthreads();
    if (active && half == 0 && lane == 0) g_cursor[n] = 0;

    const int4*   slots4 = (const int4*)(g_slot + n * CAP);   // 16B aligned
    // This warp's feature slice: 64 floats = 32 float2; lane owns 2 features.
    const float2* xs = (const float2*)x + half * 32 + lane;   // + d*64 per row

    // accumulators: 4 channels x float2 = 8 floats
    float2 a0 = make_float2(0.f, 0.f);
    float2 a1 = a0, a2 = a0, a3 = a0;

    const float4* PwTlv = g_PwT + lv * (LC * PC);   // + (lw*PC+p)

#define ACC_EDGE(W, V)                                        \
    {                                                         \
        a0.x += (W).x * (V).x; a0.y += (W).x * (V).y;         \
        a1.x += (W).y * (V).x; a1.y += (W).y * (V).y;         \
        a2.x += (W).z * (V).x; a2.y += (W).z * (V).y;         \
        a3.x += (W).w * (V).x; a3.y += (W).w * (V).y;         \
    }

    int i = 0;
    for (; i + 4 <= cnt; i += 4) {
        int4 pk = slots4[i >> 2];
        int d0 = pk.x & 0x7FFF, r0 = pk.x >> 15;
        int d1 = pk.y & 0x7FFF, r1 = pk.y >> 15;
        int d2 = pk.z & 0x7FFF, r2 = pk.z >> 15;
        int d3 = pk.w & 0x7FFF, r3 = pk.w >> 15;

        float4 w0 = __ldg(&PwTlv[r0]);              // warp-broadcast sectors
        float4 w1 = __ldg(&PwTlv[r1]);
        float4 w2 = __ldg(&PwTlv[r2]);
        float4 w3 = __ldg(&PwTlv[r3]);
        float2 v0 = __ldg(xs + d0 * (FC / 2));      // 256B/warp coalesced
        float2 v1 = __ldg(xs + d1 * (FC / 2));
        float2 v2 = __ldg(xs + d2 * (FC / 2));
        float2 v3 = __ldg(xs + d3 * (FC / 2));

        ACC_EDGE(w0, v0)
        ACC_EDGE(w1, v1)
        ACC_EDGE(w2, v2)
        ACC_EDGE(w3, v3)
    }
    for (; i < cnt; ++i) {
        int pw = g_slot[n * CAP + i];
        int d0 = pw & 0x7FFF, r0 = pw >> 15;
        float4 w0 = __ldg(&PwTlv[r0]);
        float2 v0 = __ldg(xs + d0 * (FC / 2));
        ACC_EDGE(w0, v0)
    }
#undef ACC_EDGE

    if (!active) return;

    // Epilogue: bias + float2 stores, this warp's 64-feature slice only.
    // bias element (k*LC+lv)*FC + half*64 + 2*lane  -> float2 index:
    const float2* pb = (const float2*)Pb + half * 32 + lane;
    float2*       o  = (float2*)(out + (size_t)n * (KC * FC)) + half * 32 + lane;

    float2 b0 = __ldg(pb + (0 * LC + lv) * (FC / 2));
    float2 b1 = __ldg(pb + (1 * LC + lv) * (FC / 2));
    float2 b2 = __ldg(pb + (2 * LC + lv) * (FC / 2));
    float2 b3 = __ldg(pb + (3 * LC + lv) * (FC / 2));

    a0.x += b0.x; a0.y += b0.y;
    a1.x += b1.x; a1.y += b1.y;
    a2.x += b2.x; a2.y += b2.y;
    a3.x += b3.x; a3.y += b3.y;

    o[0 * (FC / 2)] = a0;
    o[1 * (FC / 2)] = a1;
    o[2 * (FC / 2)] = a2;
    o[3 * (FC / 2)] = a3;
}

extern "C" void kernel_launch(void* const* d_in, const int* in_sizes, int n_in,
                              void* d_out, int out_size) {
    const float* x         = (const float*)d_in[0];
    const int*   labels    = (const int*)  d_in[1];
    const int*   edge_src  = (const int*)  d_in[2];
    const int*   edge_dst  = (const int*)  d_in[3];
    const int*   edge_prop = (const int*)  d_in[4];
    const float* Pw        = (const float*)d_in[5];
    const float* Pb        = (const float*)d_in[6];
    float*       out       = (float*)d_out;

    const int E = in_sizes[2];   // 640000
    (void)n_in; (void)out_size;

    k_prep_scatter<<<(E + 255) / 256, 256>>>(edge_src, edge_dst, edge_prop,
                                             labels, Pw, E);
    // 2 warps per node -> NN*2 warps -> NN*64 threads; 256-thread blocks
    k_gather<<<(NN * 64) / 256, 256>>>(x, labels, Pb, out);
}

// round 8
// speedup vs baseline: 1.4976x; 1.0588x over previous
#include <cuda_runtime.h>
#include <cuda_bf16.h>

// Rule-indexed sparse graph convolution, round 8.
//   out[n,k,f] = sum_{e: src(e)=n} W[k, lab[src], lab[dst], prop(e)] * x[dst(e), f]
//              + b[k, lab[n], f]
//
// Pipeline (2 launches):
//  1. k_prep_scatter : bucket edges by src (packed (lw*16+p)<<15 | d) +
//                      transpose Param_W -> float4 PwT. Cursors self-reset in
//                      k_gather (zero-init statics establish call-1 invariant).
//  2. k_gather : TWO warps per node, split by EDGES (alternating int4 slot
//                groups). Full 128-feature lanes (float4/lane) per warp -> no
//                duplicated decode/weight work. Partial sums combined via smem
//                + pair-scoped named barrier; warp 0 does bias + stores.

#define KC 4
#define LC 50
#define PC 16
#define FC 128
#define NN 20000
#define EE 640000
#define LLP (LC * LC * PC)    // 40000, k-stride in Param_W
#define NRULE (LC * LC * PC)  // 40000 rules: (lv*L+lw)*P+p
#define CAP 128               // slots/node; Poisson(32) -> overflow prob ~1e-35

// ---------- static scratch (allocation-free, zero-initialized) ----------
__device__ int    g_cursor[NN];                    // self-resetting (see k_gather)
__device__ __align__(16) int g_slot[NN * CAP];     // packed (lw*PC+p)<<15 | d
__device__ float4 g_PwT[NRULE];                    // {w_k0,w_k1,w_k2,w_k3} per rule

// ---------- phase 1: scatter + weight transpose (one kernel) ----------
__global__ void __launch_bounds__(256)
k_prep_scatter(const int*   __restrict__ edge_src,
               const int*   __restrict__ edge_dst,
               const int*   __restrict__ edge_prop,
               const int*   __restrict__ labels,
               const float* __restrict__ Pw,
               int E) {
    int t = blockIdx.x * blockDim.x + threadIdx.x;

    // Param_W transpose into float4-per-rule
    if (t < NRULE / 4) {
        const float4* Pw4 = (const float4*)Pw;
        float4 w0 = __ldg(&Pw4[t]);                 // k=0
        float4 w1 = __ldg(&Pw4[t + LLP / 4]);       // k=1
        float4 w2 = __ldg(&Pw4[t + 2 * LLP / 4]);   // k=2
        float4 w3 = __ldg(&Pw4[t + 3 * LLP / 4]);   // k=3
        int b = t * 4;
        g_PwT[b + 0] = make_float4(w0.x, w1.x, w2.x, w3.x);
        g_PwT[b + 1] = make_float4(w0.y, w1.y, w2.y, w3.y);
        g_PwT[b + 2] = make_float4(w0.z, w1.z, w2.z, w3.z);
        g_PwT[b + 3] = make_float4(w0.w, w1.w, w2.w, w3.w);
    }

    // edge bucketing (cursors start at zero via the self-reset invariant)
    if (t < E) {
        int s  = edge_src[t];
        int d  = edge_dst[t];
        int p  = edge_prop[t];
        int lw = __ldg(&labels[d]);
        int pk = ((lw * PC + p) << 15) | d;         // d < 32768, lw*16+p < 800
        int pos = atomicAdd(&g_cursor[s], 1);
        if (pos < CAP) g_slot[s * CAP + pos] = pk;
    }
}

// ---------- phase 2: gather, 2 warps per node (EDGE split) ----------
__global__ void __launch_bounds__(256)
k_gather(const float* __restrict__ x,
         const int*   __restrict__ labels,
         const float* __restrict__ Pb,
         float*       __restrict__ out) {
    int tid       = threadIdx.x;
    int lane      = tid & 31;
    int warpInBlk = tid >> 5;          // 0..7
    int pairInBlk = warpInBlk >> 1;    // 0..3 (node within block)
    int half      = warpInBlk & 1;     // which sibling warp
    int n         = blockIdx.x * 4 + pairInBlk;   // grid = NN/4 = 5000, exact

    __shared__ float4 sacc[4][4][32];  // [pair][channel][lane], 8 KB

    int lv  = labels[n];               // uniform per warp
    int cnt = g_cursor[n];
    if (cnt > CAP) cnt = CAP;

    const int4*   slots4 = (const int4*)(g_slot + n * CAP);   // 16B aligned
    const float4* x4     = (const float4*)x;    // row stride = 32 float4

    float4 a0 = make_float4(0.f, 0.f, 0.f, 0.f);
    float4 a1 = a0, a2 = a0, a3 = a0;

    const float4* PwTlv = g_PwT + lv * (LC * PC);   // + (lw*PC+p)

#define ACC_EDGE(W, V)                                                          \
    {                                                                           \
        a0.x += (W).x * (V).x; a0.y += (W).x * (V).y; a0.z += (W).x * (V).z; a0.w += (W).x * (V).w; \
        a1.x += (W).y * (V).x; a1.y += (W).y * (V).y; a1.z += (W).y * (V).z; a1.w += (W).y * (V).w; \
        a2.x += (W).z * (V).x; a2.y += (W).z * (V).y; a2.z += (W).z * (V).z; a2.w += (W).z * (V).w; \
        a3.x += (W).w * (V).x; a3.y += (W).w * (V).y; a3.z += (W).w * (V).z; a3.w += (W).w * (V).w; \
    }

    int nG = cnt >> 2;                 // int4 groups of 4 edges
    for (int g = half; g < nG; g += 2) {
        int4 pk = slots4[g];
        int d0 = pk.x & 0x7FFF, r0 = pk.x >> 15;
        int d1 = pk.y & 0x7FFF, r1 = pk.y >> 15;
        int d2 = pk.z & 0x7FFF, r2 = pk.z >> 15;
        int d3 = pk.w & 0x7FFF, r3 = pk.w >> 15;

        float4 w0 = __ldg(&PwTlv[r0]);          // warp-broadcast sectors
        float4 w1 = __ldg(&PwTlv[r1]);
        float4 w2 = __ldg(&PwTlv[r2]);
        float4 w3 = __ldg(&PwTlv[r3]);
        float4 v0 = __ldg(&x4[d0 * (FC / 4) + lane]);   // 512B/warp coalesced
        float4 v1 = __ldg(&x4[d1 * (FC / 4) + lane]);
        float4 v2 = __ldg(&x4[d2 * (FC / 4) + lane]);
        float4 v3 = __ldg(&x4[d3 * (FC / 4) + lane]);

        ACC_EDGE(w0, v0)
        ACC_EDGE(w1, v1)
        ACC_EDGE(w2, v2)
        ACC_EDGE(w3, v3)
    }
    if (half == 1) {                   // tail edges (cnt % 4) handled by warp 1
        for (int i = nG << 2; i < cnt; ++i) {
            int pw = g_slot[n * CAP + i];
            int d0 = pw & 0x7FFF, r0 = pw >> 15;
            float4 w0 = __ldg(&PwTlv[r0]);
            float4 v0 = __ldg(&x4[d0 * (FC / 4) + lane]);
            ACC_EDGE(w0, v0)
        }
    }
#undef ACC_EDGE

    // Combine: warp 1 dumps partials to smem; pair-scoped named barrier;
    // warp 0 adds, applies bias, stores. Barrier ids 1..4 (0 is reserved).
    if (half == 1) {
        sacc[pairInBlk][0][lane] = a0;
        sacc[pairInBlk][1][lane] = a1;
        sacc[pairInBlk][2][lane] = a2;
        sacc[pairInBlk][3][lane] = a3;
    }
    asm volatile("bar.sync %0, %1;" :: "r"(pairInBlk + 1), "r"(64) : "memory");

    if (half == 0) {
        float4 p0 = sacc[pairInBlk][0][lane];
        float4 p1 = sacc[pairInBlk][1][lane];
        float4 p2 = sacc[pairInBlk][2][lane];
        float4 p3 = sacc[pairInBlk][3][lane];

        const float4* pb = (const float4*)Pb;
        float4*       o  = (float4*)(out + (size_t)n * (KC * FC));

        float4 b0 = __ldg(&pb[(0 * LC + lv) * (FC / 4) + lane]);
        float4 b1 = __ldg(&pb[(1 * LC + lv) * (FC / 4) + lane]);
        float4 b2 = __ldg(&pb[(2 * LC + lv) * (FC / 4) + lane]);
        float4 b3 = __ldg(&pb[(3 * LC + lv) * (FC / 4) + lane]);

        a0.x += p0.x + b0.x; a0.y += p0.y + b0.y; a0.z += p0.z + b0.z; a0.w += p0.w + b0.w;
        a1.x += p1.x + b1.x; a1.y += p1.y + b1.y; a1.z += p1.z + b1.z; a1.w += p1.w + b1.w;
        a2.x += p2.x + b2.x; a2.y += p2.y + b2.y; a2.z += p2.z + b2.z; a2.w += p2.w + b2.w;
        a3.x += p3.x + b3.x; a3.y += p3.y + b3.y; a3.z += p3.z + b3.z; a3.w += p3.w + b3.w;

        o[0 * (FC / 4) + lane] = a0;
        o[1 * (FC / 4) + lane] = a1;
        o[2 * (FC / 4) + lane] = a2;
        o[3 * (FC / 4) + lane] = a3;

        // Cursor self-reset: both warps read cnt before the pair barrier,
        // so resetting after it is safe.
        if (lane == 0) g_cursor[n] = 0;
    }
}

extern "C" void kernel_launch(void* const* d_in, const int* in_sizes, int n_in,
                              void* d_out, int out_size) {
    const float* x         = (const float*)d_in[0];
    const int*   labels    = (const int*)  d_in[1];
    const int*   edge_src  = (const int*)  d_in[2];
    const int*   edge_dst  = (const int*)  d_in[3];
    const int*   edge_prop = (const int*)  d_in[4];
    const float* Pw        = (const float*)d_in[5];
    const float* Pb        = (const float*)d_in[6];
    float*       out       = (float*)d_out;

    const int E = in_sizes[2];   // 640000
    (void)n_in; (void)out_size;

    k_prep_scatter<<<(E + 255) / 256, 256>>>(edge_src, edge_dst, edge_prop,
                                             labels, Pw, E);
    // 2 warps per node, 4 nodes per 256-thread block -> NN/4 = 5000 blocks
    k_gather<<<NN / 4, 256>>>(x, labels, Pb, out);
}

// round 9
// speedup vs baseline: 1.5226x; 1.0167x over previous
#include <cuda_runtime.h>
#include <cuda_bf16.h>

// Rule-indexed sparse graph convolution, round 9.
//   out[n,k,f] = sum_{e: src(e)=n} W[k, lab[src], lab[dst], prop(e)] * x[dst(e), f]
//              + b[k, lab[n], f]
//
// Pipeline (2 launches):
//  1. k_prep_scatter : bucket edges by src (packed (lw*16+p)<<15 | d) +
//                      transpose Param_W -> float4 PwT. Cursors self-reset in
//                      k_gather (zero-init statics establish call-1 invariant).
//  2. k_gather : block = 64 threads = ONE node, 2 warps split the node's edges
//                (alternating int4 slot groups). Full 128-feature lanes
//                (float4/lane). Combine via smem + __syncthreads. Registers
//                capped by __launch_bounds__(64, 24) to lift occupancy.

#define KC 4
#define LC 50
#define PC 16
#define FC 128
#define NN 20000
#define EE 640000
#define LLP (LC * LC * PC)    // 40000, k-stride in Param_W
#define NRULE (LC * LC * PC)  // 40000 rules: (lv*L+lw)*P+p
#define CAP 128               // slots/node; Poisson(32) -> overflow prob ~1e-35

// ---------- static scratch (allocation-free, zero-initialized) ----------
__device__ int    g_cursor[NN];                    // self-resetting (see k_gather)
__device__ __align__(16) int g_slot[NN * CAP];     // packed (lw*PC+p)<<15 | d
__device__ float4 g_PwT[NRULE];                    // {w_k0,w_k1,w_k2,w_k3} per rule

// ---------- phase 1: scatter + weight transpose (one kernel) ----------
__global__ void __launch_bounds__(256)
k_prep_scatter(const int*   __restrict__ edge_src,
               const int*   __restrict__ edge_dst,
               const int*   __restrict__ edge_prop,
               const int*   __restrict__ labels,
               const float* __restrict__ Pw,
               int E) {
    int t = blockIdx.x * blockDim.x + threadIdx.x;

    // Param_W transpose into float4-per-rule
    if (t < NRULE / 4) {
        const float4* Pw4 = (const float4*)Pw;
        float4 w0 = __ldg(&Pw4[t]);                 // k=0
        float4 w1 = __ldg(&Pw4[t + LLP / 4]);       // k=1
        float4 w2 = __ldg(&Pw4[t + 2 * LLP / 4]);   // k=2
        float4 w3 = __ldg(&Pw4[t + 3 * LLP / 4]);   // k=3
        int b = t * 4;
        g_PwT[b + 0] = make_float4(w0.x, w1.x, w2.x, w3.x);
        g_PwT[b + 1] = make_float4(w0.y, w1.y, w2.y, w3.y);
        g_PwT[b + 2] = make_float4(w0.z, w1.z, w2.z, w3.z);
        g_PwT[b + 3] = make_float4(w0.w, w1.w, w2.w, w3.w);
    }

    // edge bucketing (cursors start at zero via the self-reset invariant)
    if (t < E) {
        int s  = edge_src[t];
        int d  = edge_dst[t];
        int p  = edge_prop[t];
        int lw = __ldg(&labels[d]);
        int pk = ((lw * PC + p) << 15) | d;         // d < 32768, lw*16+p < 800
        int pos = atomicAdd(&g_cursor[s], 1);
        if (pos < CAP) g_slot[s * CAP + pos] = pk;
    }
}

// ---------- phase 2: gather, block = one node, 2 edge-split warps ----------
__global__ void __launch_bounds__(64, 24)
k_gather(const float* __restrict__ x,
         const int*   __restrict__ labels,
         const float* __restrict__ Pb,
         float*       __restrict__ out) {
    int tid  = threadIdx.x;
    int lane = tid & 31;
    int half = tid >> 5;               // 0 or 1
    int n    = blockIdx.x;             // grid = NN, exact

    __shared__ float4 sacc[4][32];     // [channel][lane], 2 KB

    int lv  = labels[n];               // uniform per warp
    int cnt = g_cursor[n];
    if (cnt > CAP) cnt = CAP;

    const int4*   slots4 = (const int4*)(g_slot + n * CAP);   // 16B aligned
    const float4* xl     = (const float4*)x + lane;  // + d*32 per row

    float4 a0 = make_float4(0.f, 0.f, 0.f, 0.f);
    float4 a1 = a0, a2 = a0, a3 = a0;

    const float4* PwTlv = g_PwT + lv * (LC * PC);   // + (lw*PC+p)

#define ACC_EDGE(W, V)                                                          \
    {                                                                           \
        a0.x += (W).x * (V).x; a0.y += (W).x * (V).y; a0.z += (W).x * (V).z; a0.w += (W).x * (V).w; \
        a1.x += (W).y * (V).x; a1.y += (W).y * (V).y; a1.z += (W).y * (V).z; a1.w += (W).y * (V).w; \
        a2.x += (W).z * (V).x; a2.y += (W).z * (V).y; a2.z += (W).z * (V).z; a2.w += (W).z * (V).w; \
        a3.x += (W).w * (V).x; a3.y += (W).w * (V).y; a3.z += (W).w * (V).z; a3.w += (W).w * (V).w; \
    }

    int nG = cnt >> 2;                 // int4 groups of 4 edges
    for (int g = half; g < nG; g += 2) {
        int4 pk = slots4[g];
        int d0 = pk.x & 0x7FFF, r0 = pk.x >> 15;
        int d1 = pk.y & 0x7FFF, r1 = pk.y >> 15;
        int d2 = pk.z & 0x7FFF, r2 = pk.z >> 15;
        int d3 = pk.w & 0x7FFF, r3 = pk.w >> 15;

        float4 w0 = __ldg(&PwTlv[r0]);          // warp-broadcast sector
        float4 v0 = __ldg(&xl[d0 * (FC / 4)]);  // 512B/warp coalesced
        ACC_EDGE(w0, v0)
        float4 w1 = __ldg(&PwTlv[r1]);
        float4 v1 = __ldg(&xl[d1 * (FC / 4)]);
        ACC_EDGE(w1, v1)
        float4 w2 = __ldg(&PwTlv[r2]);
        float4 v2 = __ldg(&xl[d2 * (FC / 4)]);
        ACC_EDGE(w2, v2)
        float4 w3 = __ldg(&PwTlv[r3]);
        float4 v3 = __ldg(&xl[d3 * (FC / 4)]);
        ACC_EDGE(w3, v3)
    }
    if (half == 1) {                   // tail edges (cnt % 4) handled by warp 1
        for (int i = nG << 2; i < cnt; ++i) {
            int pw = g_slot[n * CAP + i];
            int d0 = pw & 0x7FFF, r0 = pw >> 15;
            float4 w0 = __ldg(&PwTlv[r0]);
            float4 v0 = __ldg(&xl[d0 * (FC / 4)]);
            ACC_EDGE(w0, v0)
        }
    }
#undef ACC_EDGE

    // Combine: warp 1 -> smem, sync, warp 0 adds + bias + stores.
    if (half == 1) {
        sacc[0][lane] = a0;
        sacc[1][lane] = a1;
        sacc[2][lane] = a2;
        sacc[3][lane] = a3;
    }
    __syncthreads();

    if (half == 0) {
        float4 p0 = sacc[0][lane];
        float4 p1 = sacc[1][lane];
        float4 p2 = sacc[2][lane];
        float4 p3 = sacc[3][lane];

        const float4* pb = (const float4*)Pb;
        float4*       o  = (float4*)(out + (size_t)n * (KC * FC));

        float4 b0 = __ldg(&pb[(0 * LC + lv) * (FC / 4) + lane]);
        float4 b1 = __ldg(&pb[(1 * LC + lv) * (FC / 4) + lane]);
        float4 b2 = __ldg(&pb[(2 * LC + lv) * (FC / 4) + lane]);
        float4 b3 = __ldg(&pb[(3 * LC + lv) * (FC / 4) + lane]);

        a0.x += p0.x + b0.x; a0.y += p0.y + b0.y; a0.z += p0.z + b0.z; a0.w += p0.w + b0.w;
        a1.x += p1.x + b1.x; a1.y += p1.y + b1.y; a1.z += p1.z + b1.z; a1.w += p1.w + b1.w;
        a2.x += p2.x + b2.x; a2.y += p2.y + b2.y; a2.z += p2.z + b2.z; a2.w += p2.w + b2.w;
        a3.x += p3.x + b3.x; a3.y += p3.y + b3.y; a3.z += p3.z + b3.z; a3.w += p3.w + b3.w;

        o[0 * (FC / 4) + lane] = a0;
        o[1 * (FC / 4) + lane] = a1;
        o[2 * (FC / 4) + lane] = a2;
        o[3 * (FC / 4) + lane] = a3;

        // Cursor self-reset: both warps read cnt before __syncthreads,
        // so resetting after it is safe.
        if (lane == 0) g_cursor[n] = 0;
    }
}

extern "C" void kernel_launch(void* const* d_in, const int* in_sizes, int n_in,
                              void* d_out, int out_size) {
    const float* x         = (const float*)d_in[0];
    const int*   labels    = (const int*)  d_in[1];
    const int*   edge_src  = (const int*)  d_in[2];
    const int*   edge_dst  = (const int*)  d_in[3];
    const int*   edge_prop = (const int*)  d_in[4];
    const float* Pw        = (const float*)d_in[5];
    const float* Pb        = (const float*)d_in[6];
    float*       out       = (float*)d_out;

    const int E = in_sizes[2];   // 640000
    (void)n_in; (void)out_size;

    k_prep_scatter<<<(E + 255) / 256, 256>>>(edge_src, edge_dst, edge_prop,
                                             labels, Pw, E);
    // one node per 64-thread block
    k_gather<<<NN, 64>>>(x, labels, Pb, out);
}

// round 10
// speedup vs baseline: 1.6251x; 1.0673x over previous
#include <cuda_runtime.h>
#include <cuda_fp16.h>
#include <cuda_bf16.h>

// Rule-indexed sparse graph convolution, round 10.
//   out[n,k,f] = sum_{e: src(e)=n} W[k, lab[src], lab[dst], prop(e)] * x[dst(e), f]
//              + b[k, lab[n], f]
//
// Pipeline (2 launches):
//  1. k_prep_scatter : bucket edges by src with premultiplied packing
//                      (rule<<20 | d*32), transpose Param_W -> float4 PwT,
//                      convert x -> fp16 mirror g_xh (halves gather L1 traffic).
//                      Cursors self-reset in k_gather.
//  2. k_gather : block = 64 threads = ONE node, 2 warps split the node's edges.
//                Full 128-feature lanes; lane loads uint2 (4 halves), fp32
//                accumulation. Combine via smem + __syncthreads.
//
// fp16 x path measured at rel_err 1.98e-4 in round 5 (gate: 1e-3).

#define KC 4
#define LC 50
#define PC 16
#define FC 128
#define NN 20000
#define EE 640000
#define LLP (LC * LC * PC)    // 40000, k-stride in Param_W
#define NRULE (LC * LC * PC)  // 40000 rules: (lv*L+lw)*P+p
#define CAP 128               // slots/node; Poisson(32) -> overflow prob ~1e-35
#define NF4 (NN * FC / 4)     // 640000 float4s in x

// ---------- static scratch (allocation-free, zero-initialized) ----------
__device__ int    g_cursor[NN];                    // self-resetting (see k_gather)
__device__ __align__(16) int g_slot[NN * CAP];     // packed (rule<<20) | (d*32)
__device__ float4 g_PwT[NRULE];                    // {w_k0,w_k1,w_k2,w_k3} per rule
__device__ __align__(16) __half g_xh[NN * FC];     // fp16 mirror of x (5 MB)

// ---------- phase 1: scatter + weight transpose + x->fp16 ----------
__global__ void __launch_bounds__(256)
k_prep_scatter(const int*   __restrict__ edge_src,
               const int*   __restrict__ edge_dst,
               const int*   __restrict__ edge_prop,
               const int*   __restrict__ labels,
               const float* __restrict__ Pw,
               const float* __restrict__ x,
               int E) {
    int t = blockIdx.x * blockDim.x + threadIdx.x;   // grid covers 640000

    // x -> fp16 mirror: float4 -> uint2 of 4 halves, fully coalesced
    if (t < NF4) {
        float4 v = __ldg(&((const float4*)x)[t]);
        __half2 h0 = __floats2half2_rn(v.x, v.y);
        __half2 h1 = __floats2half2_rn(v.z, v.w);
        uint2 pk;
        pk.x = *(unsigned int*)&h0;
        pk.y = *(unsigned int*)&h1;
        ((uint2*)g_xh)[t] = pk;
    }

    // Param_W transpose into float4-per-rule
    if (t < NRULE / 4) {
        const float4* Pw4 = (const float4*)Pw;
        float4 w0 = __ldg(&Pw4[t]);                 // k=0
        float4 w1 = __ldg(&Pw4[t + LLP / 4]);       // k=1
        float4 w2 = __ldg(&Pw4[t + 2 * LLP / 4]);   // k=2
        float4 w3 = __ldg(&Pw4[t + 3 * LLP / 4]);   // k=3
        int b = t * 4;
        g_PwT[b + 0] = make_float4(w0.x, w1.x, w2.x, w3.x);
        g_PwT[b + 1] = make_float4(w0.y, w1.y, w2.y, w3.y);
        g_PwT[b + 2] = make_float4(w0.z, w1.z, w2.z, w3.z);
        g_PwT[b + 3] = make_float4(w0.w, w1.w, w2.w, w3.w);
    }

    // edge bucketing (cursors start at zero via the self-reset invariant)
    if (t < E) {
        int s  = edge_src[t];
        int d  = edge_dst[t];
        int p  = edge_prop[t];
        int lw = __ldg(&labels[d]);
        // rule<<20 | d*32 : rule < 800 (10b), d*32 < 640000 (20b)
        int pk = ((lw * PC + p) << 20) | (d << 5);
        int pos = atomicAdd(&g_cursor[s], 1);
        if (pos < CAP) g_slot[s * CAP + pos] = pk;
    }
}

// ---------- phase 2: gather, block = one node, 2 edge-split warps ----------
__global__ void __launch_bounds__(64, 24)
k_gather(const int*   __restrict__ labels,
         const float* __restrict__ Pb,
         float*       __restrict__ out) {
    int tid  = threadIdx.x;
    int lane = tid & 31;
    int half = tid >> 5;               // 0 or 1
    int n    = blockIdx.x;             // grid = NN, exact

    __shared__ float4 sacc[4][32];     // [channel][lane], 2 KB

    int lv  = labels[n];               // uniform per warp
    int cnt = g_cursor[n];
    if (cnt > CAP) cnt = CAP;

    const int4*  slots4 = (const int4*)(g_slot + n * CAP);   // 16B aligned
    const uint2* xh     = (const uint2*)g_xh + lane;  // + (d*32) per row

    float4 a0 = make_float4(0.f, 0.f, 0.f, 0.f);
    float4 a1 = a0, a2 = a0, a3 = a0;

    const float4* PwTlv = g_PwT + lv * (LC * PC);   // + (lw*PC+p)

#define ACC_EDGE(W, RAW)                                                        \
    {                                                                           \
        float2 lo = __half22float2(*(__half2*)&(RAW).x);                        \
        float2 hi = __half22float2(*(__half2*)&(RAW).y);                        \
        a0.x += (W).x * lo.x; a0.y += (W).x * lo.y; a0.z += (W).x * hi.x; a0.w += (W).x * hi.y; \
        a1.x += (W).y * lo.x; a1.y += (W).y * lo.y; a1.z += (W).y * hi.x; a1.w += (W).y * hi.y; \
        a2.x += (W).z * lo.x; a2.y += (W).z * lo.y; a2.z += (W).z * hi.x; a2.w += (W).z * hi.y; \
        a3.x += (W).w * lo.x; a3.y += (W).w * lo.y; a3.z += (W).w * hi.x; a3.w += (W).w * hi.y; \
    }

    int nG = cnt >> 2;                 // int4 groups of 4 edges
    for (int g = half; g < nG; g += 2) {
        int4 pk = slots4[g];
        int o0 = pk.x & 0xFFFFF, r0 = ((unsigned)pk.x) >> 20;   // o = d*32
        int o1 = pk.y & 0xFFFFF, r1 = ((unsigned)pk.y) >> 20;
        int o2 = pk.z & 0xFFFFF, r2 = ((unsigned)pk.z) >> 20;
        int o3 = pk.w & 0xFFFFF, r3 = ((unsigned)pk.w) >> 20;

        float4 w0 = __ldg(&PwTlv[r0]);          // warp-broadcast sector
        uint2  v0 = __ldg(&xh[o0]);             // 256B/warp coalesced
        ACC_EDGE(w0, v0)
        float4 w1 = __ldg(&PwTlv[r1]);
        uint2  v1 = __ldg(&xh[o1]);
        ACC_EDGE(w1, v1)
        float4 w2 = __ldg(&PwTlv[r2]);
        uint2  v2 = __ldg(&xh[o2]);
        ACC_EDGE(w2, v2)
        float4 w3 = __ldg(&PwTlv[r3]);
        uint2  v3 = __ldg(&xh[o3]);
        ACC_EDGE(w3, v3)
    }
    if (half == 1) {                   // tail edges (cnt % 4) handled by warp 1
        for (int i = nG << 2; i < cnt; ++i) {
            int pw = g_slot[n * CAP + i];
            int o0 = pw & 0xFFFFF, r0 = ((unsigned)pw) >> 20;
            float4 w0 = __ldg(&PwTlv[r0]);
            uint2  v0 = __ldg(&xh[o0]);
            ACC_EDGE(w0, v0)
        }
    }
#undef ACC_EDGE

    // Combine: warp 1 -> smem, sync, warp 0 adds + bias + stores.
    if (half == 1) {
        sacc[0][lane] = a0;
        sacc[1][lane] = a1;
        sacc[2][lane] = a2;
        sacc[3][lane] = a3;
    }
    __syncthreads();

    if (half == 0) {
        float4 p0 = sacc[0][lane];
        float4 p1 = sacc[1][lane];
        float4 p2 = sacc[2][lane];
        float4 p3 = sacc[3][lane];

        const float4* pb = (const float4*)Pb;
        float4*       o  = (float4*)(out + (size_t)n * (KC * FC));

        float4 b0 = __ldg(&pb[(0 * LC + lv) * (FC / 4) + lane]);
        float4 b1 = __ldg(&pb[(1 * LC + lv) * (FC / 4) + lane]);
        float4 b2 = __ldg(&pb[(2 * LC + lv) * (FC / 4) + lane]);
        float4 b3 = __ldg(&pb[(3 * LC + lv) * (FC / 4) + lane]);

        a0.x += p0.x + b0.x; a0.y += p0.y + b0.y; a0.z += p0.z + b0.z; a0.w += p0.w + b0.w;
        a1.x += p1.x + b1.x; a1.y += p1.y + b1.y; a1.z += p1.z + b1.z; a1.w += p1.w + b1.w;
        a2.x += p2.x + b2.x; a2.y += p2.y + b2.y; a2.z += p2.z + b2.z; a2.w += p2.w + b2.w;
        a3.x += p3.x + b3.x; a3.y += p3.y + b3.y; a3.z += p3.z + b3.z; a3.w += p3.w + b3.w;

        o[0 * (FC / 4) + lane] = a0;
        o[1 * (FC / 4) + lane] = a1;
        o[2 * (FC / 4) + lane] = a2;
        o[3 * (FC / 4) + lane] = a3;

        // Cursor self-reset: both warps read cnt before __syncthreads,
        // so resetting after it is safe.
        if (lane == 0) g_cursor[n] = 0;
    }
}

extern "C" void kernel_launch(void* const* d_in, const int* in_sizes, int n_in,
                              void* d_out, int out_size) {
    const float* x         = (const float*)d_in[0];
    const int*   labels    = (const int*)  d_in[1];
    const int*   edge_src  = (const int*)  d_in[2];
    const int*   edge_dst  = (const int*)  d_in[3];
    const int*   edge_prop = (const int*)  d_in[4];
    const float* Pw        = (const float*)d_in[5];
    const float* Pb        = (const float*)d_in[6];
    float*       out       = (float*)d_out;

    const int E = in_sizes[2];   // 640000
    (void)n_in; (void)out_size;

    // grid covers max(E, NF4) = 640000 work items
    k_prep_scatter<<<(NF4 + 255) / 256, 256>>>(edge_src, edge_dst, edge_prop,
                                               labels, Pw, x, E);
    // one node per 64-thread block
    k_gather<<<NN, 64>>>(labels, Pb, out);
}